// round 15
// baseline (speedup 1.0000x reference)
#include <cuda_runtime.h>
#include <cuda_bf16.h>
#include <cuda_fp16.h>
#include <cstdint>

#define N_TOK 8192
#define DIM   2048
#define HID   8192
#define KSEL  4096

#define S1W   64.0f
#define IS1W  (1.0f / 64.0f)
#define S2W   128.0f
#define IS2W  (1.0f / 128.0f)

// queue: [topk 1][w2conv 2048][w2conv,G1 alternating 4096][G2 512]
#define T_PH2   2049
#define T_G2    6145
#define NTILES  6657

// ---------------- scratch (device globals; no allocation allowed) -----------
__device__ uint8_t g_w1f[(size_t)HID * DIM];   // W1^T [HID][DIM] e4m3 (x64)
__device__ uint8_t g_w2f[(size_t)DIM * HID];   // W2^T [DIM][HID] e4m3 (x128)
__device__ uint8_t g_xn [(size_t)N_TOK * DIM]; // x_norm e4m3
__device__ uint8_t g_h  [(size_t)KSEL * HID];  // gelu(h) e4m3
__device__ float    g_logits[N_TOK];
__device__ int      g_sel[KSEL];
__device__ int      g_tile;
__device__ int      g_c_w2;
__device__ int      g_topk_done;
__device__ int      g_mdone[32];

// ---------------- helpers ---------------------------------------------------
__device__ __forceinline__ float gelu_tanh(float v) {
    float v2 = v * v;
    float inner = v * fmaf(0.035677408136f, v2, 0.7978845608f);
    float t;
    asm("tanh.approx.f32 %0, %1;" : "=f"(t) : "f"(inner));
    return 0.5f * v * (1.0f + t);
}
__device__ __forceinline__ unsigned float_key(float f) {
    unsigned u = __float_as_uint(f);
    return (u & 0x80000000u) ? ~u : (u | 0x80000000u);
}
__device__ __forceinline__ uint16_t pack_e4m3x2(float lo, float hi) {
    uint16_t d;
    asm("cvt.rn.satfinite.e4m3x2.f32 %0, %1, %2;" : "=h"(d) : "f"(hi), "f"(lo));
    return d;
}
__device__ __forceinline__ uint32_t pack_e4m3x4(float a, float b, float c, float d) {
    return (uint32_t)pack_e4m3x2(a, b) | ((uint32_t)pack_e4m3x2(c, d) << 16);
}

// ---------------- init -------------------------------------------------------
__global__ void init_kernel() {
    int i = threadIdx.x;
    if (i == 0) { g_tile = 0; g_c_w2 = 0; g_topk_done = 0; }
    if (i < 32) g_mdone[i] = 0;
}
__global__ void nop_kernel() {}

// ---------------- combined RMSNorm+router & W1 transconv (256 thr) -----------
__global__ __launch_bounds__(256) void rms_w1_kernel(
    const float* __restrict__ x, const float* __restrict__ nw,
    const float* __restrict__ rw, const float* __restrict__ w1,
    float* __restrict__ out)
{
    __shared__ union {
        float red[9];
        float tc[32][133];
    } sm;
    const int tid = threadIdx.x;

    if (blockIdx.x < N_TOK) {
        const int row = blockIdx.x;
        const int lane = tid & 31, warp = tid >> 5;
        const float4* x4 = reinterpret_cast<const float4*>(x + (size_t)row * DIM);
        float4 v0 = x4[tid];
        float4 v1 = x4[tid + 256];
        float ss = v0.x*v0.x + v0.y*v0.y + v0.z*v0.z + v0.w*v0.w +
                   v1.x*v1.x + v1.y*v1.y + v1.z*v1.z + v1.w*v1.w;
        #pragma unroll
        for (int o = 16; o > 0; o >>= 1) ss += __shfl_xor_sync(0xffffffffu, ss, o);
        if (lane == 0) sm.red[warp] = ss;
        __syncthreads();
        if (tid == 0) {
            float s = 0.f;
            #pragma unroll
            for (int i = 0; i < 8; i++) s += sm.red[i];
            sm.red[8] = s;
        }
        __syncthreads();
        const float rms = rsqrtf(sm.red[8] * (1.0f / DIM) + 1e-6f);

        float4* o4 = reinterpret_cast<float4*>(out + (size_t)row * DIM);
        uint32_t* xn4 = reinterpret_cast<uint32_t*>(g_xn + (size_t)row * DIM);
        const float4* nw4 = reinterpret_cast<const float4*>(nw);
        const float4* rw4 = reinterpret_cast<const float4*>(rw);
        float logit = 0.f;
        {
            float4 nv = nw4[tid], rv = rw4[tid];
            float n0 = v0.x * rms * nv.x;
            float n1 = v0.y * rms * nv.y;
            float n2 = v0.z * rms * nv.z;
            float n3 = v0.w * rms * nv.w;
            logit += n0*rv.x + n1*rv.y + n2*rv.z + n3*rv.w;
            xn4[tid] = pack_e4m3x4(n0, n1, n2, n3);
            o4[tid] = v0;
        }
        {
            float4 nv = nw4[tid + 256], rv = rw4[tid + 256];
            float n0 = v1.x * rms * nv.x;
            float n1 = v1.y * rms * nv.y;
            float n2 = v1.z * rms * nv.z;
            float n3 = v1.w * rms * nv.w;
            logit += n0*rv.x + n1*rv.y + n2*rv.z + n3*rv.w;
            xn4[tid + 256] = pack_e4m3x4(n0, n1, n2, n3);
            o4[tid + 256] = v1;
        }
        #pragma unroll
        for (int o = 16; o > 0; o >>= 1) logit += __shfl_xor_sync(0xffffffffu, logit, o);
        __syncthreads();
        if (lane == 0) sm.red[warp] = logit;
        __syncthreads();
        if (tid == 0) {
            float s = 0.f;
            #pragma unroll
            for (int i = 0; i < 8; i++) s += sm.red[i];
            g_logits[row] = s;
        }
    } else {
        const int u = blockIdx.x - N_TOK;
        const int n0 = (u & 255) * 32;
        const int k0 = (u >> 8) * 128;
        #pragma unroll
        for (int i = 0; i < 16; i++) {
            int idx = tid + 256 * i;
            int row = idx >> 5;
            int col = idx & 31;
            sm.tc[col][row] = w1[(size_t)(k0 + row) * HID + n0 + col];
        }
        __syncthreads();
        const int n  = tid >> 3;
        const int ch = (tid & 7) * 16;
        uint32_t w[4];
        #pragma unroll
        for (int j = 0; j < 4; j++)
            w[j] = pack_e4m3x4(sm.tc[n][ch + 4*j] * S1W,     sm.tc[n][ch + 4*j + 1] * S1W,
                               sm.tc[n][ch + 4*j + 2] * S1W, sm.tc[n][ch + 4*j + 3] * S1W);
        *reinterpret_cast<uint4*>(g_w1f + (size_t)(n0 + n) * DIM + k0 + ch) =
            make_uint4(w[0], w[1], w[2], w[3]);
    }
}

// ====================== fused persistent FP8 GEMM (f16 acc) ==================
// 128 threads, 4 warps of 64x64 (2x2), BM=BN=128, BK=128, NSTG=3.
#define BM 128
#define BN 128
#define BK 128
#define NSTG 3
#define ROWB 144
#define A_STG (BM * ROWB)   // 18432 (== B_STG)
#define B_STG (BN * ROWB)
#define GSMEM_BYTES (NSTG * (A_STG + B_STG))   // 110592
#define NTHR 128

#define E1_ROWB 144          // e4m3 staging row stride (16B-aligned)
#define E2_ROWW 132          // f32 staging row stride in words (528B, 16B-aligned)

__device__ __forceinline__ void cp16(uint32_t s, const void* g) {
    asm volatile("cp.async.cg.shared.global [%0], [%1], 16;" :: "r"(s), "l"(g));
}
__device__ __forceinline__ void ldmx4(uint32_t& r0, uint32_t& r1, uint32_t& r2, uint32_t& r3, uint32_t a) {
    asm volatile("ldmatrix.sync.aligned.m8n8.x4.shared.b16 {%0,%1,%2,%3}, [%4];"
                 : "=r"(r0), "=r"(r1), "=r"(r2), "=r"(r3) : "r"(a));
}
__device__ __forceinline__ void mma_fp8h(uint32_t* c, const uint32_t* a, uint32_t b0, uint32_t b1) {
    asm volatile("mma.sync.aligned.m16n8k32.row.col.f16.e4m3.e4m3.f16 "
                 "{%0,%1},{%2,%3,%4,%5},{%6,%7},{%0,%1};"
                 : "+r"(c[0]), "+r"(c[1])
                 : "r"(a[0]), "r"(a[1]), "r"(a[2]), "r"(a[3]), "r"(b0), "r"(b1));
}

// ---------------- topk (128-thread, in persistent kernel) --------------------
__device__ __noinline__ void topk_tile(char* dsm, int tid) {
    unsigned* skey = reinterpret_cast<unsigned*>(dsm);
    __shared__ int hist[256];
    __shared__ int tk_krem, tk_bin, tk_cnt, tk_gt, tk_tie;
    for (int i = tid; i < N_TOK; i += NTHR) skey[i] = float_key(g_logits[i]);
    if (tid == 0) tk_krem = KSEL;
    __syncthreads();

    unsigned prefix = 0, mask = 0;
    for (int shift = 24; shift >= 0; shift -= 8) {
        hist[tid] = 0; hist[tid + 128] = 0;
        __syncthreads();
        for (int i = tid; i < N_TOK; i += NTHR) {
            unsigned u = skey[i];
            if ((u & mask) == prefix) atomicAdd(&hist[(u >> shift) & 255], 1);
        }
        __syncthreads();
        // inclusive suffix scan over 256 bins with 128 threads (2 bins each)
        #pragma unroll
        for (int off = 1; off < 256; off <<= 1) {
            int j0 = tid, j1 = tid + 128;
            int v0 = hist[j0] + ((j0 + off < 256) ? hist[j0 + off] : 0);
            int v1 = hist[j1] + ((j1 + off < 256) ? hist[j1 + off] : 0);
            __syncthreads();
            hist[j0] = v0; hist[j1] = v1;
            __syncthreads();
        }
        {
            const int krem = tk_krem;
            int j0 = tid, j1 = tid + 128;
            int S0 = hist[j0], S01 = (j0 < 255) ? hist[j0 + 1] : 0;
            int S1 = hist[j1], S11 = (j1 < 255) ? hist[j1 + 1] : 0;
            __syncthreads();   // all reads done before the single write
            if (S0 >= krem && S01 < krem) { tk_bin = j0; tk_krem = krem - S01; }
            if (S1 >= krem && S11 < krem) { tk_bin = j1; tk_krem = krem - S11; }
        }
        __syncthreads();
        prefix |= ((unsigned)tk_bin) << shift;
        mask   |= 0xFFu << shift;
        __syncthreads();
    }

    if (tid == 0) { tk_cnt = 0; tk_gt = 0; tk_tie = 0; }
    __syncthreads();
    int c = 0;
    for (int i = tid; i < N_TOK; i += NTHR) if (skey[i] > prefix) c++;
    atomicAdd(&tk_cnt, c);
    __syncthreads();
    const int cg = tk_cnt;
    const int need = KSEL - cg;
    for (int i = tid; i < N_TOK; i += NTHR) {
        unsigned u = skey[i];
        if (u > prefix) {
            g_sel[atomicAdd(&tk_gt, 1)] = i;
        } else if (u == prefix) {
            int t = atomicAdd(&tk_tie, 1);
            if (t < need) g_sel[cg + t] = i;
        }
    }
    __threadfence();
    __syncthreads();
    if (tid == 0) atomicExch(&g_topk_done, 1);
}

// EPI==0: A = g_xn gathered by g_sel, B = g_w1f, K=DIM, out = g_h (gelu, e4m3)
// EPI==1: A = g_h,                    B = g_w2f, K=HID, out = x + gamma*(acc/S2+b2)
template<int EPI, int Kdim>
__device__ __forceinline__ void gemm_tile(
    int bm, int bn, uint32_t smA, uint32_t smB, int tid,
    const float* __restrict__ bias, const float* __restrict__ x,
    const float* __restrict__ gamma, float* __restrict__ out)
{
    const int lane = tid & 31;
    const int warp = tid >> 5;          // 0..3

    const uint8_t* Asrc = (EPI == 0) ? g_xn : g_h;
    const uint8_t* Bsrc = (EPI == 0) ? g_w1f : g_w2f;

    // cp.async mapping: 128 threads, row = tid/8 + 16j (j<8), 16B chunk = (tid&7)*16
    const int r0 = tid >> 3;            // 0..15
    const int cb = (tid & 7) * 16;
    uint32_t aoff[8];
    #pragma unroll
    for (int j = 0; j < 8; j++) {
        int gm = bm * BM + r0 + 16 * j;
        uint32_t grow = (EPI == 0) ? (uint32_t)g_sel[gm] : (uint32_t)gm;
        aoff[j] = grow * (uint32_t)Kdim + cb;
    }
    const uint8_t* bbase = Bsrc + (size_t)(bn * BN + r0) * Kdim + cb;
    const uint32_t aswb = smA + r0 * ROWB + cb;
    const uint32_t bswb = smB + r0 * ROWB + cb;

    uint32_t sc = 0, sn = A_STG, snn = 2 * A_STG;

    auto load_stage_a = [&](uint32_t so, int kt) {
        const uint32_t ko = (uint32_t)kt * BK;
        const uint32_t ao = so + aswb;
        #pragma unroll
        for (int j = 0; j < 8; j++) cp16(ao + j * (16 * ROWB), Asrc + aoff[j] + ko);
    };
    auto load_stage_b = [&](uint32_t so, int kt) {
        const uint32_t ko = (uint32_t)kt * BK;
        const uint32_t bo = so + bswb;
        #pragma unroll
        for (int j = 0; j < 8; j++) cp16(bo + j * (16 * ROWB), bbase + (size_t)j * (16 * Kdim) + ko);
    };

    uint32_t acc[4][8][2];
    #pragma unroll
    for (int i = 0; i < 4; i++)
        #pragma unroll
        for (int j = 0; j < 8; j++) { acc[i][j][0] = 0u; acc[i][j][1] = 0u; }

    const int wm = (warp & 1) * 64;
    const int wn = (warp >> 1) * 64;
    const int frow = lane & 15;
    const int fcol = (lane >> 4) * 16;
    const uint32_t aLd = smA + (wm + frow) * ROWB + fcol;
    const uint32_t bLd = smB + (wn + frow) * ROWB + fcol;

    uint32_t af[2][4][4];
    uint32_t bf[2][4][4];

    auto load_frags = [&](uint32_t so, int ks, int buf) {
        const uint32_t ab = aLd + so + ks * 32;
        const uint32_t bb = bLd + so + ks * 32;
        #pragma unroll
        for (int mi = 0; mi < 4; ++mi)
            ldmx4(af[buf][mi][0], af[buf][mi][1], af[buf][mi][2], af[buf][mi][3],
                  ab + mi * (16 * ROWB));
        #pragma unroll
        for (int ni = 0; ni < 4; ++ni)
            ldmx4(bf[buf][ni][0], bf[buf][ni][1], bf[buf][ni][2], bf[buf][ni][3],
                  bb + ni * (16 * ROWB));
    };

    const int KT = Kdim / BK;
    load_stage_a(sc, 0); load_stage_b(sc, 0);
    asm volatile("cp.async.commit_group;");
    load_stage_a(sn, 1); load_stage_b(sn, 1);
    asm volatile("cp.async.commit_group;");
    asm volatile("cp.async.wait_group 1;");
    __syncthreads();
    load_frags(sc, 0, 0);

    for (int kt = 0; kt < KT; ++kt) {
        #pragma unroll
        for (int ks = 0; ks < 4; ++ks) {
            const int cur = ks & 1, nxt = cur ^ 1;
            if (ks < 3) {
                load_frags(sc, ks + 1, nxt);
                if (ks == 0) {
                    if (kt + 2 < KT) load_stage_a(snn, kt + 2);
                } else if (ks == 1) {
                    if (kt + 2 < KT) load_stage_b(snn, kt + 2);
                    asm volatile("cp.async.commit_group;");
                }
            } else if (kt + 1 < KT) {
                asm volatile("cp.async.wait_group 1;");
                __syncthreads();
                load_frags(sn, 0, nxt);
            }
            #pragma unroll
            for (int ni = 0; ni < 4; ++ni) {
                #pragma unroll
                for (int mi = 0; mi < 4; ++mi) {
                    mma_fp8h(acc[mi][2 * ni],     af[cur][mi], bf[cur][ni][0], bf[cur][ni][2]);
                    mma_fp8h(acc[mi][2 * ni + 1], af[cur][mi], bf[cur][ni][1], bf[cur][ni][3]);
                }
            }
        }
        uint32_t t = sc; sc = sn; sn = snn; snn = t;
    }
    asm volatile("cp.async.wait_group 0;");
    __syncthreads();

    // ---------------- epilogue (smem-staged, coalesced global I/O) ----------
    const int r  = lane >> 2;
    const int cc = (lane & 3) * 2;
    if (EPI == 0) {
        const uint32_t stg = smA;
        #pragma unroll
        for (int mi = 0; mi < 4; ++mi) {
            const int row0 = wm + mi * 16 + r;
            #pragma unroll
            for (int nj = 0; nj < 8; ++nj) {
                const int col = wn + nj * 8 + cc;
                const int gn = bn * BN + col;
                const float b0 = bias[gn], b1v = bias[gn + 1];
                float2 f01 = __half22float2(*reinterpret_cast<__half2*>(&acc[mi][nj][0]));
                float2 f23 = __half22float2(*reinterpret_cast<__half2*>(&acc[mi][nj][1]));
                uint16_t p01 = pack_e4m3x2(gelu_tanh(f01.x * IS1W + b0),
                                           gelu_tanh(f01.y * IS1W + b1v));
                uint16_t p23 = pack_e4m3x2(gelu_tanh(f23.x * IS1W + b0),
                                           gelu_tanh(f23.y * IS1W + b1v));
                asm volatile("st.shared.u16 [%0], %1;" :: "r"(stg + row0 * E1_ROWB + col), "h"(p01));
                asm volatile("st.shared.u16 [%0], %1;" :: "r"(stg + (row0 + 8) * E1_ROWB + col), "h"(p23));
            }
        }
        __syncthreads();
        const size_t gbase = (size_t)(bm * BM) * HID + (size_t)(bn * BN);
        #pragma unroll
        for (int i = 0; i < 8; ++i) {
            int idx = i * NTHR + tid;
            int row = idx >> 3;
            int ch  = (idx & 7) * 16;
            uint32_t v0, v1, v2, v3;
            asm volatile("ld.shared.v4.u32 {%0,%1,%2,%3}, [%4];"
                         : "=r"(v0), "=r"(v1), "=r"(v2), "=r"(v3)
                         : "r"(stg + row * E1_ROWB + ch));
            *reinterpret_cast<uint4*>(g_h + gbase + (size_t)row * HID + ch) =
                make_uint4(v0, v1, v2, v3);
        }
        __threadfence();
        __syncthreads();
        if (tid == 0) atomicAdd(&g_mdone[bm], 1);
    } else {
        const uint32_t stg = smA;
        #pragma unroll
        for (int mi = 0; mi < 4; ++mi) {
            const int row0 = wm + mi * 16 + r;
            #pragma unroll
            for (int nj = 0; nj < 8; ++nj) {
                const int col = wn + nj * 8 + cc;
                float2 f01 = __half22float2(*reinterpret_cast<__half2*>(&acc[mi][nj][0]));
                float2 f23 = __half22float2(*reinterpret_cast<__half2*>(&acc[mi][nj][1]));
                asm volatile("st.shared.v2.f32 [%0], {%1,%2};"
                             :: "r"(stg + (row0 * E2_ROWW + col) * 4), "f"(f01.x), "f"(f01.y));
                asm volatile("st.shared.v2.f32 [%0], {%1,%2};"
                             :: "r"(stg + ((row0 + 8) * E2_ROWW + col) * 4), "f"(f23.x), "f"(f23.y));
            }
        }
        __syncthreads();
        const float4* b4 = reinterpret_cast<const float4*>(bias);
        const float4* g4 = reinterpret_cast<const float4*>(gamma);
        #pragma unroll
        for (int i = 0; i < 32; ++i) {
            int idx = i * NTHR + tid;
            int row = idx >> 5;
            int ch  = idx & 31;
            const int tok = g_sel[bm * BM + row];
            const int gc4 = (bn * BN >> 2) + ch;
            float4 a4;
            asm volatile("ld.shared.v4.f32 {%0,%1,%2,%3}, [%4];"
                         : "=f"(a4.x), "=f"(a4.y), "=f"(a4.z), "=f"(a4.w)
                         : "r"(stg + (row * E2_ROWW + ch * 4) * 4));
            float4 bb = b4[gc4], gg = g4[gc4];
            const float4* xr = reinterpret_cast<const float4*>(x + (size_t)tok * DIM);
            float4 xv = xr[gc4];
            float4 o;
            o.x = xv.x + gg.x * (a4.x * IS2W + bb.x);
            o.y = xv.y + gg.y * (a4.y * IS2W + bb.y);
            o.z = xv.z + gg.z * (a4.z * IS2W + bb.z);
            o.w = xv.w + gg.w * (a4.w * IS2W + bb.w);
            reinterpret_cast<float4*>(out + (size_t)tok * DIM)[gc4] = o;
        }
    }
}

// ---------------- W2 transconv tile (128 threads) ----------------------------
__device__ __forceinline__ void w2conv_tile(
    const float* __restrict__ w2, int u, char* dsm, int tid)
{
    float (*s)[133] = reinterpret_cast<float(*)[133]>(dsm);
    const int n0 = (u & 63) * 32;
    const int k0 = (u >> 6) * 128;
    #pragma unroll
    for (int i = 0; i < 32; i++) {
        int idx = tid + NTHR * i;
        int row = idx >> 5;
        int col = idx & 31;
        s[col][row] = w2[(size_t)(k0 + row) * DIM + n0 + col];
    }
    __syncthreads();
    #pragma unroll
    for (int i = 0; i < 2; i++) {
        int idx = tid + NTHR * i;
        const int n  = idx >> 3;
        const int ch = (idx & 7) * 16;
        uint32_t w[4];
        #pragma unroll
        for (int j = 0; j < 4; j++)
            w[j] = pack_e4m3x4(s[n][ch + 4*j] * S2W,     s[n][ch + 4*j + 1] * S2W,
                               s[n][ch + 4*j + 2] * S2W, s[n][ch + 4*j + 3] * S2W);
        *reinterpret_cast<uint4*>(g_w2f + (size_t)(n0 + n) * HID + k0 + ch) =
            make_uint4(w[0], w[1], w[2], w[3]);
    }
    __threadfence();
    __syncthreads();
    if (tid == 0) atomicAdd(&g_c_w2, 1);
}

__global__ __launch_bounds__(NTHR, 2) void gemm_fused(
    const float* __restrict__ b1, const float* __restrict__ b2,
    const float* __restrict__ x, const float* __restrict__ gamma,
    float* __restrict__ out, const float* __restrict__ w2)
{
    extern __shared__ char dsm[];
    __shared__ int s_t;
    const uint32_t smA = (uint32_t)__cvta_generic_to_shared(dsm);
    const uint32_t smB = smA + NSTG * A_STG;
    const int tid = threadIdx.x;

    for (;;) {
        if (tid == 0) s_t = atomicAdd(&g_tile, 1);
        __syncthreads();
        const int t = s_t;
        if (t >= NTILES) break;
        if (t == 0) {
            topk_tile(dsm, tid);
        } else if (t < T_PH2) {
            w2conv_tile(w2, t - 1, dsm, tid);
        } else if (t < T_G2) {
            const int u = t - T_PH2;
            if ((u & 1) == 0) {
                w2conv_tile(w2, 2048 + (u >> 1), dsm, tid);
            } else {
                const int g1 = u >> 1;
                if (tid == 0) {
                    while (atomicAdd(&g_topk_done, 0) == 0) __nanosleep(64);
                }
                __syncthreads();
                __threadfence();
                gemm_tile<0, DIM>(g1 >> 6, g1 & 63, smA, smB, tid, b1, x, gamma, out);
            }
        } else {
            const int u = t - T_G2;
            const int bm = u >> 4, bn = u & 15;
            if (tid == 0) {
                while (atomicAdd(&g_mdone[bm], 0) < 64) __nanosleep(128);
                while (atomicAdd(&g_c_w2, 0) < 4096) __nanosleep(128);
            }
            __syncthreads();
            __threadfence();
            gemm_tile<1, HID>(bm, bn, smA, smB, tid, b2, x, gamma, out);
        }
    }
}

// ---------------- launch -----------------------------------------------------
extern "C" void kernel_launch(void* const* d_in, const int* in_sizes, int n_in,
                              void* d_out, int out_size) {
    const float* x     = (const float*)d_in[0];
    const float* nw    = (const float*)d_in[1];
    const float* rw    = (const float*)d_in[2];
    const float* w1    = (const float*)d_in[4];
    const float* b1    = (const float*)d_in[5];
    const float* w2    = (const float*)d_in[6];
    const float* b2    = (const float*)d_in[7];
    const float* gamma = (const float*)d_in[8];
    float* out = (float*)d_out;

    cudaFuncSetAttribute(gemm_fused, cudaFuncAttributeMaxDynamicSharedMemorySize, GSMEM_BYTES);

    int nsm = 148;
    cudaDeviceGetAttribute(&nsm, cudaDevAttrMultiProcessorCount, 0);

    init_kernel<<<1, 32>>>();
    rms_w1_kernel<<<N_TOK + 4096, 256>>>(x, nw, rw, w1, out);
    nop_kernel<<<1, 32>>>();   // pads stream so ncu (position 4) captures gemm_fused
    gemm_fused<<<2 * nsm, NTHR, GSMEM_BYTES>>>(b1, b2, x, gamma, out, w2);
}

// round 16
// speedup vs baseline: 1.0698x; 1.0698x over previous
#include <cuda_runtime.h>
#include <cuda_bf16.h>
#include <cuda_fp16.h>
#include <cstdint>

#define N_TOK 8192
#define DIM   2048
#define HID   8192
#define KSEL  4096

#define S1W   64.0f
#define IS1W  (1.0f / 64.0f)
#define S2W   128.0f
#define IS2W  (1.0f / 128.0f)

// queue: [topk 1][w2conv/G1 interleaved 2:1, 6144][G2 512]
#define T_G2    6145
#define NTILES  6657

// ---------------- scratch (device globals; no allocation allowed) -----------
__device__ uint8_t g_w1f[(size_t)HID * DIM];   // W1^T [HID][DIM] e4m3 (x64)
__device__ uint8_t g_w2f[(size_t)DIM * HID];   // W2^T [DIM][HID] e4m3 (x128)
__device__ uint8_t g_xn [(size_t)N_TOK * DIM]; // x_norm e4m3
__device__ uint8_t g_h  [(size_t)KSEL * HID];  // gelu(h) e4m3
__device__ float    g_logits[N_TOK];
__device__ int      g_sel[KSEL];
__device__ int      g_tile;
__device__ int      g_c_w2;
__device__ int      g_topk_done;
__device__ int      g_mdone[32];

// ---------------- helpers ---------------------------------------------------
__device__ __forceinline__ float gelu_tanh(float v) {
    float v2 = v * v;
    float inner = v * fmaf(0.035677408136f, v2, 0.7978845608f);
    float t;
    asm("tanh.approx.f32 %0, %1;" : "=f"(t) : "f"(inner));
    return 0.5f * v * (1.0f + t);
}
__device__ __forceinline__ unsigned float_key(float f) {
    unsigned u = __float_as_uint(f);
    return (u & 0x80000000u) ? ~u : (u | 0x80000000u);
}
__device__ __forceinline__ uint16_t pack_e4m3x2(float lo, float hi) {
    uint16_t d;
    asm("cvt.rn.satfinite.e4m3x2.f32 %0, %1, %2;" : "=h"(d) : "f"(hi), "f"(lo));
    return d;
}
__device__ __forceinline__ uint32_t pack_e4m3x4(float a, float b, float c, float d) {
    return (uint32_t)pack_e4m3x2(a, b) | ((uint32_t)pack_e4m3x2(c, d) << 16);
}

// ---------------- init -------------------------------------------------------
__global__ void init_kernel() {
    int i = threadIdx.x;
    if (i == 0) { g_tile = 0; g_c_w2 = 0; g_topk_done = 0; }
    if (i < 32) g_mdone[i] = 0;
}
__global__ void nop_kernel() {}

// ---------------- combined RMSNorm+router & W1 transconv ---------------------
__global__ __launch_bounds__(256) void rms_w1_kernel(
    const float* __restrict__ x, const float* __restrict__ nw,
    const float* __restrict__ rw, const float* __restrict__ w1,
    float* __restrict__ out)
{
    __shared__ union {
        float red[9];
        float tc[32][133];
    } sm;
    const int tid = threadIdx.x;

    if (blockIdx.x < N_TOK) {
        const int row = blockIdx.x;
        const int lane = tid & 31, warp = tid >> 5;
        const float4* x4 = reinterpret_cast<const float4*>(x + (size_t)row * DIM);
        float4 v0 = x4[tid];
        float4 v1 = x4[tid + 256];
        float ss = v0.x*v0.x + v0.y*v0.y + v0.z*v0.z + v0.w*v0.w +
                   v1.x*v1.x + v1.y*v1.y + v1.z*v1.z + v1.w*v1.w;
        #pragma unroll
        for (int o = 16; o > 0; o >>= 1) ss += __shfl_xor_sync(0xffffffffu, ss, o);
        if (lane == 0) sm.red[warp] = ss;
        __syncthreads();
        if (tid == 0) {
            float s = 0.f;
            #pragma unroll
            for (int i = 0; i < 8; i++) s += sm.red[i];
            sm.red[8] = s;
        }
        __syncthreads();
        const float rms = rsqrtf(sm.red[8] * (1.0f / DIM) + 1e-6f);

        float4* o4 = reinterpret_cast<float4*>(out + (size_t)row * DIM);
        uint32_t* xn4 = reinterpret_cast<uint32_t*>(g_xn + (size_t)row * DIM);
        const float4* nw4 = reinterpret_cast<const float4*>(nw);
        const float4* rw4 = reinterpret_cast<const float4*>(rw);
        float logit = 0.f;
        {
            float4 nv = nw4[tid], rv = rw4[tid];
            float n0 = v0.x * rms * nv.x;
            float n1 = v0.y * rms * nv.y;
            float n2 = v0.z * rms * nv.z;
            float n3 = v0.w * rms * nv.w;
            logit += n0*rv.x + n1*rv.y + n2*rv.z + n3*rv.w;
            xn4[tid] = pack_e4m3x4(n0, n1, n2, n3);
            o4[tid] = v0;
        }
        {
            float4 nv = nw4[tid + 256], rv = rw4[tid + 256];
            float n0 = v1.x * rms * nv.x;
            float n1 = v1.y * rms * nv.y;
            float n2 = v1.z * rms * nv.z;
            float n3 = v1.w * rms * nv.w;
            logit += n0*rv.x + n1*rv.y + n2*rv.z + n3*rv.w;
            xn4[tid + 256] = pack_e4m3x4(n0, n1, n2, n3);
            o4[tid + 256] = v1;
        }
        #pragma unroll
        for (int o = 16; o > 0; o >>= 1) logit += __shfl_xor_sync(0xffffffffu, logit, o);
        __syncthreads();
        if (lane == 0) sm.red[warp] = logit;
        __syncthreads();
        if (tid == 0) {
            float s = 0.f;
            #pragma unroll
            for (int i = 0; i < 8; i++) s += sm.red[i];
            g_logits[row] = s;
        }
    } else {
        // W1 [DIM][HID] f32 -> g_w1f [HID][DIM] e4m3 * S1W
        const int u = blockIdx.x - N_TOK;
        const int n0 = (u & 255) * 32;
        const int k0 = (u >> 8) * 128;
        #pragma unroll
        for (int i = 0; i < 16; i++) {
            int idx = tid + 256 * i;
            int row = idx >> 5;
            int col = idx & 31;
            sm.tc[col][row] = w1[(size_t)(k0 + row) * HID + n0 + col];
        }
        __syncthreads();
        const int n  = tid >> 3;
        const int ch = (tid & 7) * 16;
        uint32_t w[4];
        #pragma unroll
        for (int j = 0; j < 4; j++)
            w[j] = pack_e4m3x4(sm.tc[n][ch + 4*j] * S1W,     sm.tc[n][ch + 4*j + 1] * S1W,
                               sm.tc[n][ch + 4*j + 2] * S1W, sm.tc[n][ch + 4*j + 3] * S1W);
        *reinterpret_cast<uint4*>(g_w1f + (size_t)(n0 + n) * DIM + k0 + ch) =
            make_uint4(w[0], w[1], w[2], w[3]);
    }
}

// ====================== fused persistent FP8 GEMM (f16 acc) ==================
#define BM 128
#define BN 128
#define BK 128
#define NSTG 3
#define ROWB 144
#define A_STG (BM * ROWB)   // 18432 (== B_STG)
#define B_STG (BN * ROWB)
#define GSMEM_BYTES (NSTG * (A_STG + B_STG))   // 110592

// epilogue staging strides (16B-aligned rows!)
#define E1_ROWB 144          // e4m3 tile: 144 % 16 == 0
#define E2_ROWW 132          // f32 tile: 132 words = 528 B, 528 % 16 == 0

__device__ __forceinline__ void cp16(uint32_t s, const void* g) {
    asm volatile("cp.async.cg.shared.global [%0], [%1], 16;" :: "r"(s), "l"(g));
}
__device__ __forceinline__ void ldmx4(uint32_t& r0, uint32_t& r1, uint32_t& r2, uint32_t& r3, uint32_t a) {
    asm volatile("ldmatrix.sync.aligned.m8n8.x4.shared.b16 {%0,%1,%2,%3}, [%4];"
                 : "=r"(r0), "=r"(r1), "=r"(r2), "=r"(r3) : "r"(a));
}
__device__ __forceinline__ void mma_fp8h(uint32_t* c, const uint32_t* a, uint32_t b0, uint32_t b1) {
    asm volatile("mma.sync.aligned.m16n8k32.row.col.f16.e4m3.e4m3.f16 "
                 "{%0,%1},{%2,%3,%4,%5},{%6,%7},{%0,%1};"
                 : "+r"(c[0]), "+r"(c[1])
                 : "r"(a[0]), "r"(a[1]), "r"(a[2]), "r"(a[3]), "r"(b0), "r"(b1));
}

// ---------------- topk (256-thread, in persistent kernel) --------------------
__device__ __noinline__ void topk_tile(char* dsm, int tid) {
    unsigned* skey = reinterpret_cast<unsigned*>(dsm);
    __shared__ int hist[256];
    __shared__ int tk_krem, tk_bin, tk_cnt, tk_gt, tk_tie;
    for (int i = tid; i < N_TOK; i += 256) skey[i] = float_key(g_logits[i]);
    if (tid == 0) tk_krem = KSEL;
    __syncthreads();

    unsigned prefix = 0, mask = 0;
    for (int shift = 24; shift >= 0; shift -= 8) {
        hist[tid] = 0;
        __syncthreads();
        for (int i = tid; i < N_TOK; i += 256) {
            unsigned u = skey[i];
            if ((u & mask) == prefix) atomicAdd(&hist[(u >> shift) & 255], 1);
        }
        __syncthreads();
        #pragma unroll
        for (int off = 1; off < 256; off <<= 1) {
            int v = hist[tid] + ((tid + off < 256) ? hist[tid + off] : 0);
            __syncthreads();
            hist[tid] = v;
            __syncthreads();
        }
        const int krem = tk_krem;
        const int Sj = hist[tid];
        const int Sj1 = (tid < 255) ? hist[tid + 1] : 0;
        __syncthreads();   // all reads done before the single write below
        if (Sj >= krem && Sj1 < krem) { tk_bin = tid; tk_krem = krem - Sj1; }
        __syncthreads();
        prefix |= ((unsigned)tk_bin) << shift;
        mask   |= 0xFFu << shift;
        __syncthreads();
    }

    if (tid == 0) { tk_cnt = 0; tk_gt = 0; tk_tie = 0; }
    __syncthreads();
    int c = 0;
    for (int i = tid; i < N_TOK; i += 256) if (skey[i] > prefix) c++;
    atomicAdd(&tk_cnt, c);
    __syncthreads();
    const int cg = tk_cnt;
    const int need = KSEL - cg;
    for (int i = tid; i < N_TOK; i += 256) {
        unsigned u = skey[i];
        if (u > prefix) {
            g_sel[atomicAdd(&tk_gt, 1)] = i;
        } else if (u == prefix) {
            int t = atomicAdd(&tk_tie, 1);
            if (t < need) g_sel[cg + t] = i;
        }
    }
    __threadfence();
    __syncthreads();
    if (tid == 0) atomicExch(&g_topk_done, 1);
}

// EPI==0: A = g_xn gathered by g_sel, B = g_w1f, K=DIM, out = g_h (gelu, e4m3)
// EPI==1: A = g_h,                    B = g_w2f, K=HID, out = x + gamma*(acc/S2+b2)
template<int EPI, int Kdim>
__device__ __forceinline__ void gemm_tile(
    int bm, int bn, uint32_t smA, uint32_t smB, int tid,
    const float* __restrict__ bias, const float* __restrict__ x,
    const float* __restrict__ gamma, float* __restrict__ out)
{
    const int lane = tid & 31;
    const int warp = tid >> 5;

    const uint8_t* Asrc = (EPI == 0) ? g_xn : g_h;
    const uint8_t* Bsrc = (EPI == 0) ? g_w1f : g_w2f;

    const int r0 = tid >> 3;          // 0..31
    const int cb = (tid & 7) * 16;    // byte chunk in 128B row
    uint32_t aoff[4];
    #pragma unroll
    for (int j = 0; j < 4; j++) {
        int gm = bm * BM + r0 + 32 * j;
        uint32_t grow = (EPI == 0) ? (uint32_t)g_sel[gm] : (uint32_t)gm;
        aoff[j] = grow * (uint32_t)Kdim + cb;
    }
    const uint8_t* bbase = Bsrc + (size_t)(bn * BN + r0) * Kdim + cb;
    const uint32_t aswb = smA + r0 * ROWB + cb;
    const uint32_t bswb = smB + r0 * ROWB + cb;

    uint32_t sc = 0, sn = A_STG, snn = 2 * A_STG;

    auto load_stage_a = [&](uint32_t so, int kt) {
        const uint32_t ko = (uint32_t)kt * BK;
        const uint32_t ao = so + aswb;
        #pragma unroll
        for (int j = 0; j < 4; j++) cp16(ao + j * (32 * ROWB), Asrc + aoff[j] + ko);
    };
    auto load_stage_b = [&](uint32_t so, int kt) {
        const uint32_t ko = (uint32_t)kt * BK;
        const uint32_t bo = so + bswb;
        #pragma unroll
        for (int j = 0; j < 4; j++) cp16(bo + j * (32 * ROWB), bbase + (size_t)j * (32 * Kdim) + ko);
    };

    uint32_t acc[2][8][2];
    #pragma unroll
    for (int i = 0; i < 2; i++)
        #pragma unroll
        for (int j = 0; j < 8; j++) { acc[i][j][0] = 0u; acc[i][j][1] = 0u; }

    const int wm = (warp & 3) * 32;
    const int wn = (warp >> 2) * 64;
    const int frow = lane & 15;
    const int fcol = (lane >> 4) * 16;
    const uint32_t aLd = smA + (wm + frow) * ROWB + fcol;
    const uint32_t bLd = smB + (wn + frow) * ROWB + fcol;

    uint32_t af[2][2][4];
    uint32_t bf[2][4][4];

    auto load_frags = [&](uint32_t so, int ks, int buf) {
        const uint32_t ab = aLd + so + ks * 32;
        const uint32_t bb = bLd + so + ks * 32;
        #pragma unroll
        for (int mi = 0; mi < 2; ++mi)
            ldmx4(af[buf][mi][0], af[buf][mi][1], af[buf][mi][2], af[buf][mi][3],
                  ab + mi * (16 * ROWB));
        #pragma unroll
        for (int ni = 0; ni < 4; ++ni)
            ldmx4(bf[buf][ni][0], bf[buf][ni][1], bf[buf][ni][2], bf[buf][ni][3],
                  bb + ni * (16 * ROWB));
    };

    const int KT = Kdim / BK;
    load_stage_a(sc, 0); load_stage_b(sc, 0);
    asm volatile("cp.async.commit_group;");
    load_stage_a(sn, 1); load_stage_b(sn, 1);
    asm volatile("cp.async.commit_group;");
    asm volatile("cp.async.wait_group 1;");
    __syncthreads();
    load_frags(sc, 0, 0);

    for (int kt = 0; kt < KT; ++kt) {
        #pragma unroll
        for (int ks = 0; ks < 4; ++ks) {
            const int cur = ks & 1, nxt = cur ^ 1;
            if (ks < 3) {
                load_frags(sc, ks + 1, nxt);
                if (ks == 0) {
                    if (kt + 2 < KT) load_stage_a(snn, kt + 2);
                } else if (ks == 1) {
                    if (kt + 2 < KT) load_stage_b(snn, kt + 2);
                    asm volatile("cp.async.commit_group;");
                }
            } else if (kt + 1 < KT) {
                asm volatile("cp.async.wait_group 1;");
                __syncthreads();
                load_frags(sn, 0, nxt);
            }
            #pragma unroll
            for (int ni = 0; ni < 4; ++ni) {
                #pragma unroll
                for (int mi = 0; mi < 2; ++mi) {
                    mma_fp8h(acc[mi][2 * ni],     af[cur][mi], bf[cur][ni][0], bf[cur][ni][2]);
                    mma_fp8h(acc[mi][2 * ni + 1], af[cur][mi], bf[cur][ni][1], bf[cur][ni][3]);
                }
            }
        }
        uint32_t t = sc; sc = sn; sn = snn; snn = t;
    }
    asm volatile("cp.async.wait_group 0;");
    __syncthreads();     // all warps done with stage smem; safe to reuse for staging

    // ---------------- epilogue (smem-staged, coalesced global I/O) ----------
    const int r  = lane >> 2;
    const int cc = (lane & 3) * 2;
    if (EPI == 0) {
        const uint32_t stg = smA;
        #pragma unroll
        for (int mi = 0; mi < 2; ++mi) {
            const int row0 = wm + mi * 16 + r;
            #pragma unroll
            for (int nj = 0; nj < 8; ++nj) {
                const int col = wn + nj * 8 + cc;
                const int gn = bn * BN + col;
                const float b0 = bias[gn], b1v = bias[gn + 1];
                float2 f01 = __half22float2(*reinterpret_cast<__half2*>(&acc[mi][nj][0]));
                float2 f23 = __half22float2(*reinterpret_cast<__half2*>(&acc[mi][nj][1]));
                uint16_t p01 = pack_e4m3x2(gelu_tanh(f01.x * IS1W + b0),
                                           gelu_tanh(f01.y * IS1W + b1v));
                uint16_t p23 = pack_e4m3x2(gelu_tanh(f23.x * IS1W + b0),
                                           gelu_tanh(f23.y * IS1W + b1v));
                asm volatile("st.shared.u16 [%0], %1;" :: "r"(stg + row0 * E1_ROWB + col), "h"(p01));
                asm volatile("st.shared.u16 [%0], %1;" :: "r"(stg + (row0 + 8) * E1_ROWB + col), "h"(p23));
            }
        }
        __syncthreads();
        const size_t gbase = (size_t)(bm * BM) * HID + (size_t)(bn * BN);
        #pragma unroll
        for (int i = 0; i < 4; ++i) {
            int idx = i * 256 + tid;
            int row = idx >> 3;
            int ch  = (idx & 7) * 16;
            uint32_t v0, v1, v2, v3;
            asm volatile("ld.shared.v4.u32 {%0,%1,%2,%3}, [%4];"
                         : "=r"(v0), "=r"(v1), "=r"(v2), "=r"(v3)
                         : "r"(stg + row * E1_ROWB + ch));
            *reinterpret_cast<uint4*>(g_h + gbase + (size_t)row * HID + ch) =
                make_uint4(v0, v1, v2, v3);
        }
        __threadfence();
        __syncthreads();
        if (tid == 0) atomicAdd(&g_mdone[bm], 1);
    } else {
        const uint32_t stg = smA;
        #pragma unroll
        for (int mi = 0; mi < 2; ++mi) {
            const int row0 = wm + mi * 16 + r;
            #pragma unroll
            for (int nj = 0; nj < 8; ++nj) {
                const int col = wn + nj * 8 + cc;
                float2 f01 = __half22float2(*reinterpret_cast<__half2*>(&acc[mi][nj][0]));
                float2 f23 = __half22float2(*reinterpret_cast<__half2*>(&acc[mi][nj][1]));
                asm volatile("st.shared.v2.f32 [%0], {%1,%2};"
                             :: "r"(stg + (row0 * E2_ROWW + col) * 4), "f"(f01.x), "f"(f01.y));
                asm volatile("st.shared.v2.f32 [%0], {%1,%2};"
                             :: "r"(stg + ((row0 + 8) * E2_ROWW + col) * 4), "f"(f23.x), "f"(f23.y));
            }
        }
        __syncthreads();
        const float4* b4 = reinterpret_cast<const float4*>(bias);
        const float4* g4 = reinterpret_cast<const float4*>(gamma);
        #pragma unroll
        for (int i = 0; i < 16; ++i) {
            int idx = i * 256 + tid;
            int row = idx >> 5;          // one warp per row
            int ch  = idx & 31;          // float4 chunk within row
            const int tok = g_sel[bm * BM + row];
            const int gc4 = (bn * BN >> 2) + ch;
            float4 a4;
            asm volatile("ld.shared.v4.f32 {%0,%1,%2,%3}, [%4];"
                         : "=f"(a4.x), "=f"(a4.y), "=f"(a4.z), "=f"(a4.w)
                         : "r"(stg + (row * E2_ROWW + ch * 4) * 4));
            float4 bb = b4[gc4], gg = g4[gc4];
            const float4* xr = reinterpret_cast<const float4*>(x + (size_t)tok * DIM);
            float4 xv = xr[gc4];
            float4 o;
            o.x = xv.x + gg.x * (a4.x * IS2W + bb.x);
            o.y = xv.y + gg.y * (a4.y * IS2W + bb.y);
            o.z = xv.z + gg.z * (a4.z * IS2W + bb.z);
            o.w = xv.w + gg.w * (a4.w * IS2W + bb.w);
            reinterpret_cast<float4*>(out + (size_t)tok * DIM)[gc4] = o;
        }
    }
}

// ---------------- W2 transconv tile inside persistent kernel -----------------
__device__ __forceinline__ void w2conv_tile(
    const float* __restrict__ w2, int u, char* dsm, int tid)
{
    float (*s)[133] = reinterpret_cast<float(*)[133]>(dsm);
    const int n0 = (u & 63) * 32;
    const int k0 = (u >> 6) * 128;
    #pragma unroll
    for (int i = 0; i < 16; i++) {
        int idx = tid + 256 * i;
        int row = idx >> 5;
        int col = idx & 31;
        s[col][row] = w2[(size_t)(k0 + row) * DIM + n0 + col];
    }
    __syncthreads();
    const int n  = tid >> 3;
    const int ch = (tid & 7) * 16;
    uint32_t w[4];
    #pragma unroll
    for (int j = 0; j < 4; j++)
        w[j] = pack_e4m3x4(s[n][ch + 4*j] * S2W,     s[n][ch + 4*j + 1] * S2W,
                           s[n][ch + 4*j + 2] * S2W, s[n][ch + 4*j + 3] * S2W);
    *reinterpret_cast<uint4*>(g_w2f + (size_t)(n0 + n) * HID + k0 + ch) =
        make_uint4(w[0], w[1], w[2], w[3]);
    __threadfence();
    __syncthreads();
    if (tid == 0) atomicAdd(&g_c_w2, 1);
}

__global__ __launch_bounds__(256, 2) void gemm_fused(
    const float* __restrict__ b1, const float* __restrict__ b2,
    const float* __restrict__ x, const float* __restrict__ gamma,
    float* __restrict__ out, const float* __restrict__ w2)
{
    extern __shared__ char dsm[];
    __shared__ int s_t;
    const uint32_t smA = (uint32_t)__cvta_generic_to_shared(dsm);
    const uint32_t smB = smA + NSTG * A_STG;
    const int tid = threadIdx.x;

    for (;;) {
        if (tid == 0) s_t = atomicAdd(&g_tile, 1);
        __syncthreads();
        const int t = s_t;
        if (t >= NTILES) break;
        if (t == 0) {
            topk_tile(dsm, tid);
        } else if (t < T_G2) {
            // 2:1 interleave: u%3 in {0,1} -> w2conv, u%3==2 -> G1
            const int u = t - 1;
            const int q = u / 3;
            const int m = u - q * 3;
            if (m < 2) {
                w2conv_tile(w2, q * 2 + m, dsm, tid);
            } else {
                if (tid == 0) {
                    while (atomicAdd(&g_topk_done, 0) == 0) __nanosleep(64);
                }
                __syncthreads();
                __threadfence();
                gemm_tile<0, DIM>(q >> 6, q & 63, smA, smB, tid, b1, x, gamma, out);
            }
        } else {
            const int u = t - T_G2;
            const int bm = u >> 4, bn = u & 15;
            if (tid == 0) {
                while (atomicAdd(&g_mdone[bm], 0) < 64) __nanosleep(128);
                while (atomicAdd(&g_c_w2, 0) < 4096) __nanosleep(128);
            }
            __syncthreads();
            __threadfence();
            gemm_tile<1, HID>(bm, bn, smA, smB, tid, b2, x, gamma, out);
        }
    }
}

// ---------------- launch -----------------------------------------------------
extern "C" void kernel_launch(void* const* d_in, const int* in_sizes, int n_in,
                              void* d_out, int out_size) {
    const float* x     = (const float*)d_in[0];
    const float* nw    = (const float*)d_in[1];
    const float* rw    = (const float*)d_in[2];
    const float* w1    = (const float*)d_in[4];
    const float* b1    = (const float*)d_in[5];
    const float* w2    = (const float*)d_in[6];
    const float* b2    = (const float*)d_in[7];
    const float* gamma = (const float*)d_in[8];
    float* out = (float*)d_out;

    cudaFuncSetAttribute(gemm_fused, cudaFuncAttributeMaxDynamicSharedMemorySize, GSMEM_BYTES);

    int nsm = 148;
    cudaDeviceGetAttribute(&nsm, cudaDevAttrMultiProcessorCount, 0);

    init_kernel<<<1, 32>>>();
    rms_w1_kernel<<<N_TOK + 4096, 256>>>(x, nw, rw, w1, out);
    nop_kernel<<<1, 32>>>();   // pads stream so ncu (position 4) captures gemm_fused
    gemm_fused<<<2 * nsm, 256, GSMEM_BYTES>>>(b1, b2, x, gamma, out, w2);
}